// round 2
// baseline (speedup 1.0000x reference)
#include <cuda_runtime.h>
#include <math.h>

// Problem constants
#define BATCH 4
#define SEQ   2048
#define DIM   1024   // D_IN == D_OUT == head dim

#define BM 128
#define BN 128
#define BK 8
#define TM 8
#define TN 8
#define THREADS 256

// Scratch (allocation-free: __device__ globals)
__device__ float g_q[BATCH * SEQ * DIM];          // 32 MB
__device__ float g_k[BATCH * SEQ * DIM];          // 32 MB
__device__ float g_v[BATCH * SEQ * DIM];          // 32 MB
__device__ float g_s[BATCH * SEQ * SEQ];          // 64 MB (scores / probs)

// ---------------------------------------------------------------------------
// C[M,N] = scale * (A[M,K] @ B[N,K]^T) + bias   (both operands K-major)
// Used for: QKV projections (bias, scale=1) and Q@K^T scores
// (bias=nullptr, scale=1/32, causal block-skip).
// blockIdx.z selects batch via strides.
// ---------------------------------------------------------------------------
__global__ void __launch_bounds__(THREADS)
gemm_nt(const float* __restrict__ A, const float* __restrict__ Bm,
        const float* __restrict__ bias, float* __restrict__ C,
        int M, int N, int K, float scale, int causal,
        long long sA, long long sB, long long sC)
{
    int bx = blockIdx.x, by = blockIdx.y, bz = blockIdx.z;
    if (causal && bx > by) return;           // whole tile above diagonal: never read

    A  += (size_t)bz * sA;
    Bm += (size_t)bz * sB;
    C  += (size_t)bz * sC;

    __shared__ float As[BK][BM];
    __shared__ float Bs[BK][BN];

    int tid  = threadIdx.x;
    int lrow = tid >> 1;                     // 0..127
    int lcol = (tid & 1) * 4;                // 0 or 4
    int tx   = tid & 15, ty = tid >> 4;

    const float* Ab = A  + (size_t)by * BM * K + (size_t)lrow * K + lcol;
    const float* Bb = Bm + (size_t)bx * BN * K + (size_t)lrow * K + lcol;

    float acc[TM][TN];
#pragma unroll
    for (int i = 0; i < TM; i++)
#pragma unroll
        for (int j = 0; j < TN; j++) acc[i][j] = 0.0f;

    for (int k0 = 0; k0 < K; k0 += BK) {
        float4 av = *(const float4*)(Ab + k0);
        float4 bv = *(const float4*)(Bb + k0);
        As[lcol + 0][lrow] = av.x; As[lcol + 1][lrow] = av.y;
        As[lcol + 2][lrow] = av.z; As[lcol + 3][lrow] = av.w;
        Bs[lcol + 0][lrow] = bv.x; Bs[lcol + 1][lrow] = bv.y;
        Bs[lcol + 2][lrow] = bv.z; Bs[lcol + 3][lrow] = bv.w;
        __syncthreads();

#pragma unroll
        for (int kk = 0; kk < BK; kk++) {
            float af[TM], bf[TN];
#pragma unroll
            for (int i = 0; i < TM; i++) af[i] = As[kk][ty * TM + i];
#pragma unroll
            for (int j = 0; j < TN; j++) bf[j] = Bs[kk][tx * TN + j];
#pragma unroll
            for (int i = 0; i < TM; i++)
#pragma unroll
                for (int j = 0; j < TN; j++)
                    acc[i][j] = fmaf(af[i], bf[j], acc[i][j]);
        }
        __syncthreads();
    }

#pragma unroll
    for (int i = 0; i < TM; i++) {
        int row = by * BM + ty * TM + i;
#pragma unroll
        for (int j = 0; j < TN; j += 4) {
            int col = bx * BN + tx * TN + j;
            float4 v;
            v.x = acc[i][j + 0] * scale;
            v.y = acc[i][j + 1] * scale;
            v.z = acc[i][j + 2] * scale;
            v.w = acc[i][j + 3] * scale;
            if (bias) {
                v.x += bias[col + 0]; v.y += bias[col + 1];
                v.z += bias[col + 2]; v.w += bias[col + 3];
            }
            *(float4*)(C + (size_t)row * N + col) = v;
        }
    }
}

// ---------------------------------------------------------------------------
// C[M,N] = A[M,K] @ B[K,N]   (A row-major K-inner, B row-major N-inner)
// Used for P @ V. causalK: limit K-loop to the causal boundary of this M-tile
// (softmax wrote zeros above the diagonal, but we skip the all-zero tiles).
// ---------------------------------------------------------------------------
__global__ void __launch_bounds__(THREADS)
gemm_nn(const float* __restrict__ A, const float* __restrict__ Bm,
        float* __restrict__ C,
        int M, int N, int K, int causalK,
        long long sA, long long sB, long long sC)
{
    int bx = blockIdx.x, by = blockIdx.y, bz = blockIdx.z;
    A  += (size_t)bz * sA;
    Bm += (size_t)bz * sB;
    C  += (size_t)bz * sC;

    __shared__ float As[BK][BM];
    __shared__ float Bs[BK][BN];

    int tid  = threadIdx.x;
    int arow = tid >> 1;                 // 0..127
    int acol = (tid & 1) * 4;            // 0 / 4
    int brow = tid >> 5;                 // 0..7
    int bcol = (tid & 31) * 4;           // 0..124
    int tx   = tid & 15, ty = tid >> 4;

    const float* Ab = A  + (size_t)by * BM * K + (size_t)arow * K + acol;
    const float* Bb = Bm + (size_t)brow * N + (size_t)bx * BN + bcol;

    int kend = causalK ? min(K, (by + 1) * BM) : K;

    float acc[TM][TN];
#pragma unroll
    for (int i = 0; i < TM; i++)
#pragma unroll
        for (int j = 0; j < TN; j++) acc[i][j] = 0.0f;

    for (int k0 = 0; k0 < kend; k0 += BK) {
        float4 av = *(const float4*)(Ab + k0);
        float4 bv = *(const float4*)(Bb + (size_t)k0 * N);
        As[acol + 0][arow] = av.x; As[acol + 1][arow] = av.y;
        As[acol + 2][arow] = av.z; As[acol + 3][arow] = av.w;
        *(float4*)&Bs[brow][bcol] = bv;
        __syncthreads();

#pragma unroll
        for (int kk = 0; kk < BK; kk++) {
            float af[TM], bf[TN];
#pragma unroll
            for (int i = 0; i < TM; i++) af[i] = As[kk][ty * TM + i];
#pragma unroll
            for (int j = 0; j < TN; j++) bf[j] = Bs[kk][tx * TN + j];
#pragma unroll
            for (int i = 0; i < TM; i++)
#pragma unroll
                for (int j = 0; j < TN; j++)
                    acc[i][j] = fmaf(af[i], bf[j], acc[i][j]);
        }
        __syncthreads();
    }

#pragma unroll
    for (int i = 0; i < TM; i++) {
        int row = by * BM + ty * TM + i;
#pragma unroll
        for (int j = 0; j < TN; j += 4) {
            int col = bx * BN + tx * TN + j;
            float4 v;
            v.x = acc[i][j + 0]; v.y = acc[i][j + 1];
            v.z = acc[i][j + 2]; v.w = acc[i][j + 3];
            *(float4*)(C + (size_t)row * N + col) = v;
        }
    }
}

// ---------------------------------------------------------------------------
// Causal row softmax in-place on scores [BATCH, SEQ, SEQ].
// Row r: softmax over [0, r]; zero-fill (r, SEQ).
// One block per row, 256 threads.
// ---------------------------------------------------------------------------
__global__ void __launch_bounds__(256)
causal_softmax(float* __restrict__ S, int seq)
{
    int r = blockIdx.x;
    int b = blockIdx.y;
    float* row = S + ((size_t)b * seq + (size_t)r) * seq;
    int n = r + 1;
    int tid = threadIdx.x;

    __shared__ float red[256];

    // pass 1: max
    float m = -1e30f;
    for (int j = tid; j < n; j += 256) m = fmaxf(m, row[j]);
    red[tid] = m; __syncthreads();
    for (int s = 128; s > 0; s >>= 1) {
        if (tid < s) red[tid] = fmaxf(red[tid], red[tid + s]);
        __syncthreads();
    }
    m = red[0]; __syncthreads();

    // pass 2: sum of exp, caching exps in registers (<= 8 per thread)
    float ev[8];
    int cnt = 0;
    float sum = 0.0f;
    for (int j = tid; j < n; j += 256) {
        float e = __expf(row[j] - m);
        ev[cnt++] = e;
        sum += e;
    }
    red[tid] = sum; __syncthreads();
    for (int s = 128; s > 0; s >>= 1) {
        if (tid < s) red[tid] += red[tid + s];
        __syncthreads();
    }
    float inv = 1.0f / red[0];

    // pass 3: write probabilities, zero the masked tail
    cnt = 0;
    for (int j = tid; j < n; j += 256) row[j] = ev[cnt++] * inv;
    for (int j = n + tid; j < seq; j += 256) row[j] = 0.0f;
}

// ---------------------------------------------------------------------------
extern "C" void kernel_launch(void* const* d_in, const int* in_sizes, int n_in,
                              void* d_out, int out_size)
{
    const float* X  = (const float*)d_in[0];
    const float* Wq = (const float*)d_in[1];
    const float* bq = (const float*)d_in[2];
    const float* Wk = (const float*)d_in[3];
    const float* bk = (const float*)d_in[4];
    const float* Wv = (const float*)d_in[5];
    const float* bv = (const float*)d_in[6];
    float* out = (float*)d_out;

    float *qp, *kp, *vp, *sp;
    cudaGetSymbolAddress((void**)&qp, g_q);
    cudaGetSymbolAddress((void**)&kp, g_k);
    cudaGetSymbolAddress((void**)&vp, g_v);
    cudaGetSymbolAddress((void**)&sp, g_s);

    const int M = BATCH * SEQ;               // 8192 flattened rows
    const long long sQK = (long long)SEQ * DIM;   // per-batch q/k/v stride
    const long long sSS = (long long)SEQ * SEQ;   // per-batch score stride

    // 1) QKV projections: [8192,1024] @ [1024,1024]^T + bias
    {
        dim3 grid(DIM / BN, M / BM, 1);
        gemm_nt<<<grid, THREADS>>>(X, Wq, bq, qp, M, DIM, DIM, 1.0f, 0, 0, 0, 0);
        gemm_nt<<<grid, THREADS>>>(X, Wk, bk, kp, M, DIM, DIM, 1.0f, 0, 0, 0, 0);
        gemm_nt<<<grid, THREADS>>>(X, Wv, bv, vp, M, DIM, DIM, 1.0f, 0, 0, 0, 0);
    }

    // 2) scores = (Q @ K^T) / sqrt(1024), causal tiles only
    {
        dim3 grid(SEQ / BN, SEQ / BM, BATCH);
        gemm_nt<<<grid, THREADS>>>(qp, kp, nullptr, sp, SEQ, SEQ, DIM,
                                   0.03125f, 1, sQK, sQK, sSS);
    }

    // 3) causal softmax rows (writes zeros above diagonal)
    {
        dim3 grid(SEQ, BATCH);
        causal_softmax<<<grid, 256>>>(sp, SEQ);
    }

    // 4) out = P @ V  (K-loop limited to causal boundary per M-tile)
    {
        dim3 grid(DIM / BN, SEQ / BM, BATCH);
        gemm_nn<<<grid, THREADS>>>(sp, vp, out, SEQ, DIM, SEQ, 1,
                                   sSS, sQK, sQK);
    }
}

// round 5
// speedup vs baseline: 2.4425x; 2.4425x over previous
#include <cuda_runtime.h>
#include <cuda_fp16.h>
#include <cstdint>
#include <math.h>

// Problem constants
#define BATCH 4
#define SEQ   2048
#define DIM   1024

#define BM 128
#define BN 128
#define KC 32            // fp32 K elements per stage
#define THREADS 256

// flags
#define F_CAUSAL_SKIP  1
#define F_CAUSAL_KLIM  2
#define F_TRANS_STORE  4

// Scratch (allocation-free)
__device__ float g_q[BATCH * SEQ * DIM];
__device__ float g_k[BATCH * SEQ * DIM];
__device__ float g_vt[BATCH * DIM * SEQ];     // V transposed [b][d][s]
__device__ float g_s[BATCH * SEQ * SEQ];

__device__ __forceinline__ uint32_t smem_u32(const void* p) {
    uint32_t a;
    asm("{ .reg .u64 t; cvta.to.shared.u64 t, %1; cvt.u32.u64 %0, t; }" : "=r"(a) : "l"(p));
    return a;
}

#define LDMATRIX_X4(r0, r1, r2, r3, addr)                                      \
    asm volatile("ldmatrix.sync.aligned.m8n8.x4.shared.b16 {%0,%1,%2,%3}, [%4];" \
        : "=r"(r0), "=r"(r1), "=r"(r2), "=r"(r3) : "r"(addr))

#define MMA16816(d0, d1, d2, d3, a0, a1, a2, a3, b0, b1)                       \
    asm volatile("mma.sync.aligned.m16n8k16.row.col.f32.f16.f16.f32 "          \
        "{%0,%1,%2,%3},{%4,%5,%6,%7},{%8,%9},{%0,%1,%2,%3};"                   \
        : "+f"(d0), "+f"(d1), "+f"(d2), "+f"(d3)                               \
        : "r"(a0), "r"(a1), "r"(a2), "r"(a3), "r"(b0), "r"(b1))

// fp16 hi/lo split of two fp32 values -> packed half2 words
__device__ __forceinline__ void split2(float x, float y, uint32_t& hi, uint32_t& lo) {
    __half hx = __float2half_rn(x), hy = __float2half_rn(y);
    __half2 h2 = __halves2half2(hx, hy);
    hi = *reinterpret_cast<uint32_t*>(&h2);
    float rx = x - __half2float(hx);
    float ry = y - __half2float(hy);
    __half2 l2 = __floats2half2_rn(rx, ry);
    lo = *reinterpret_cast<uint32_t*>(&l2);
}

// SW64 swizzle for 64-byte rows (KC=32 halfs)
__device__ __forceinline__ uint32_t sw64(uint32_t off) {
    return off ^ ((off >> 3) & 0x30);
}

// ---------------------------------------------------------------------------
// NT GEMM via mma.sync fp16 hi/lo split: C = scale * (A @ B^T) + bias
// A [M,K], B [N,K], both fp32 K-major. blockIdx.z batches via strides.
// ---------------------------------------------------------------------------
__global__ void __launch_bounds__(THREADS, 1)
tc_gemm(const float* __restrict__ A, const float* __restrict__ B,
        const float* __restrict__ bias, float* __restrict__ C,
        int K, int ldA, int ldB, int ldC, float scale, int flags,
        long long sA, long long sB, long long sC)
{
    const int bx = blockIdx.x, by = blockIdx.y, bz = blockIdx.z;
    if ((flags & F_CAUSAL_SKIP) && bx > by) return;

    A += (size_t)bz * sA;
    B += (size_t)bz * sB;
    C += (size_t)bz * sC;

    // 4 tiles of [128 rows][32 halfs] = 8KB each, SW64-swizzled
    __shared__ __align__(1024) __half sAh[BM * KC];
    __shared__ __align__(1024) __half sAl[BM * KC];
    __shared__ __align__(1024) __half sBh[BN * KC];
    __shared__ __align__(1024) __half sBl[BN * KC];

    const int tid  = threadIdx.x;
    const int lane = tid & 31;
    const int wid  = tid >> 5;
    const int wm   = wid & 1;          // 2 m-groups of 64 rows
    const int wn   = wid >> 1;         // 4 n-groups of 32 cols

    int kend = K;
    if (flags & F_CAUSAL_KLIM) kend = min(K, (by + 1) * BM);
    const int nkb = kend / KC;

    const float* Abase = A + (size_t)by * BM * ldA;
    const float* Bbase = B + (size_t)bx * BN * ldB;

    const uint32_t uAh = smem_u32(sAh), uAl = smem_u32(sAl);
    const uint32_t uBh = smem_u32(sBh), uBl = smem_u32(sBl);

    // per-thread load coords: idx = it*256 + tid -> row = idx/8, q = idx%8
    const int lrow = tid >> 3;          // +32 per it
    const int lq   = tid & 7;           // float4 index along K

    float acc[4][4][4];
#pragma unroll
    for (int i = 0; i < 4; i++)
#pragma unroll
        for (int j = 0; j < 4; j++)
#pragma unroll
            for (int c = 0; c < 4; c++) acc[i][j][c] = 0.0f;

    // ldmatrix lane-address components (within an 8KB tile)
    const int lr  = lane & 7;
    const int grp = lane >> 3;
    const int lm_row_off = lr + ((grp & 1) << 3);     // row within 16-row tile
    const int lm_col_off = (grp >> 1) << 4;           // 0 or 16 bytes (k half)

    float4 pa[4], pb[4];
    // prefetch chunk 0
#pragma unroll
    for (int it = 0; it < 4; it++) {
        int r = lrow + it * 32;
        pa[it] = *(const float4*)(Abase + (size_t)r * ldA + lq * 4);
        pb[it] = *(const float4*)(Bbase + (size_t)r * ldB + lq * 4);
    }

    for (int kb = 0; kb < nkb; kb++) {
        // ---- convert + swizzled STS of prefetched chunk ----
#pragma unroll
        for (int it = 0; it < 4; it++) {
            int r = lrow + it * 32;
            uint32_t off = r * 64 + lq * 8;             // bytes in [128][32-half] tile
            uint32_t sw  = sw64(off);
            uint32_t h0, h1, l0, l1;
            split2(pa[it].x, pa[it].y, h0, l0);
            split2(pa[it].z, pa[it].w, h1, l1);
            *(uint2*)((char*)sAh + sw) = make_uint2(h0, h1);
            *(uint2*)((char*)sAl + sw) = make_uint2(l0, l1);
            split2(pb[it].x, pb[it].y, h0, l0);
            split2(pb[it].z, pb[it].w, h1, l1);
            *(uint2*)((char*)sBh + sw) = make_uint2(h0, h1);
            *(uint2*)((char*)sBl + sw) = make_uint2(l0, l1);
        }
        __syncthreads();

        // ---- prefetch next chunk while MMAs run ----
        if (kb + 1 < nkb) {
            const int k0 = (kb + 1) * KC;
#pragma unroll
            for (int it = 0; it < 4; it++) {
                int r = lrow + it * 32;
                pa[it] = *(const float4*)(Abase + (size_t)r * ldA + k0 + lq * 4);
                pb[it] = *(const float4*)(Bbase + (size_t)r * ldB + k0 + lq * 4);
            }
        }

        // ---- MMA: 2 k16 steps on this stage ----
#pragma unroll
        for (int ks = 0; ks < 2; ks++) {
            const uint32_t kbyte = ks * 32 + lm_col_off;

            uint32_t bh[2][4], bl[2][4];
#pragma unroll
            for (int ng = 0; ng < 2; ng++) {
                int nrow = wn * 32 + ng * 16 + lm_row_off;
                uint32_t off = sw64(nrow * 64 + kbyte);
                LDMATRIX_X4(bh[ng][0], bh[ng][1], bh[ng][2], bh[ng][3], uBh + off);
                LDMATRIX_X4(bl[ng][0], bl[ng][1], bl[ng][2], bl[ng][3], uBl + off);
            }

#pragma unroll
            for (int mt = 0; mt < 4; mt++) {
                int mrow = wm * 64 + mt * 16 + lm_row_off;
                uint32_t off = sw64(mrow * 64 + kbyte);
                uint32_t ah[4], al[4];
                LDMATRIX_X4(ah[0], ah[1], ah[2], ah[3], uAh + off);
                LDMATRIX_X4(al[0], al[1], al[2], al[3], uAl + off);

#pragma unroll
                for (int nt = 0; nt < 4; nt++) {
                    const int ng = nt >> 1, s = nt & 1;
                    float* d = acc[mt][nt];
                    // hi*hi + hi*lo + lo*hi  (lo*lo dropped, ~2^-22)
                    MMA16816(d[0], d[1], d[2], d[3],
                             ah[0], ah[1], ah[2], ah[3], bh[ng][s], bh[ng][s + 2]);
                    MMA16816(d[0], d[1], d[2], d[3],
                             ah[0], ah[1], ah[2], ah[3], bl[ng][s], bl[ng][s + 2]);
                    MMA16816(d[0], d[1], d[2], d[3],
                             al[0], al[1], al[2], al[3], bh[ng][s], bh[ng][s + 2]);
                }
            }
        }
        __syncthreads();
    }

    // ---- epilogue ----
    const int r0 = by * BM + wm * 64 + (lane >> 2);
    const int c0 = bx * BN + wn * 32 + ((lane & 3) << 1);

    if (!(flags & F_TRANS_STORE)) {
#pragma unroll
        for (int mt = 0; mt < 4; mt++) {
#pragma unroll
            for (int nt = 0; nt < 4; nt++) {
                int row = r0 + mt * 16;
                int col = c0 + nt * 8;
                float b0 = bias ? bias[col] : 0.0f;
                float b1 = bias ? bias[col + 1] : 0.0f;
                float2 v0 = make_float2(acc[mt][nt][0] * scale + b0,
                                        acc[mt][nt][1] * scale + b1);
                float2 v1 = make_float2(acc[mt][nt][2] * scale + b0,
                                        acc[mt][nt][3] * scale + b1);
                *(float2*)(C + (size_t)row * ldC + col)       = v0;
                *(float2*)(C + (size_t)(row + 8) * ldC + col) = v1;
            }
        }
    } else {
        // V transposed store: C layout [b][d][s], row is flattened token index
#pragma unroll
        for (int mt = 0; mt < 4; mt++) {
            int row = r0 + mt * 16;
            int b  = row >> 11;
            int s  = row & (SEQ - 1);
            float* dst0 = C + (size_t)b * DIM * SEQ + s;
            float* dst1 = C + (size_t)b * DIM * SEQ + s + 8;   // row+8 same batch (BM=128 block)
#pragma unroll
            for (int nt = 0; nt < 4; nt++) {
                int col = c0 + nt * 8;
                float b0 = bias[col], b1 = bias[col + 1];
                dst0[(size_t)col * SEQ]       = acc[mt][nt][0] * scale + b0;
                dst0[(size_t)(col + 1) * SEQ] = acc[mt][nt][1] * scale + b1;
                dst1[(size_t)col * SEQ]       = acc[mt][nt][2] * scale + b0;
                dst1[(size_t)(col + 1) * SEQ] = acc[mt][nt][3] * scale + b1;
            }
        }
    }
}

// ---------------------------------------------------------------------------
// Causal row softmax in-place on scores [BATCH, SEQ, SEQ].
// 256 threads x 8 iters covers SEQ=2048 exactly (ev[8] cache is exact-fit).
// ---------------------------------------------------------------------------
__global__ void __launch_bounds__(256)
causal_softmax(float* __restrict__ S, int seq)
{
    int r = blockIdx.x;
    int b = blockIdx.y;
    float* row = S + ((size_t)b * seq + (size_t)r) * seq;
    int n = r + 1;
    int tid = threadIdx.x;

    __shared__ float red[256];

    float m = -1e30f;
    for (int j = tid; j < n; j += 256) m = fmaxf(m, row[j]);
    red[tid] = m; __syncthreads();
    for (int s = 128; s > 0; s >>= 1) {
        if (tid < s) red[tid] = fmaxf(red[tid], red[tid + s]);
        __syncthreads();
    }
    m = red[0]; __syncthreads();

    float ev[8];
    int cnt = 0;
    float sum = 0.0f;
    for (int j = tid; j < n; j += 256) {
        float e = __expf(row[j] - m);
        ev[cnt++] = e;
        sum += e;
    }
    red[tid] = sum; __syncthreads();
    for (int s = 128; s > 0; s >>= 1) {
        if (tid < s) red[tid] += red[tid + s];
        __syncthreads();
    }
    float inv = 1.0f / red[0];

    cnt = 0;
    for (int j = tid; j < n; j += 256) row[j] = ev[cnt++] * inv;
    for (int j = n + tid; j < seq; j += 256) row[j] = 0.0f;
}

// ---------------------------------------------------------------------------
extern "C" void kernel_launch(void* const* d_in, const int* in_sizes, int n_in,
                              void* d_out, int out_size)
{
    const float* X  = (const float*)d_in[0];
    const float* Wq = (const float*)d_in[1];
    const float* bq = (const float*)d_in[2];
    const float* Wk = (const float*)d_in[3];
    const float* bk = (const float*)d_in[4];
    const float* Wv = (const float*)d_in[5];
    const float* bv = (const float*)d_in[6];
    float* out = (float*)d_out;

    float *qp, *kp, *vtp, *sp;
    cudaGetSymbolAddress((void**)&qp, g_q);
    cudaGetSymbolAddress((void**)&kp, g_k);
    cudaGetSymbolAddress((void**)&vtp, g_vt);
    cudaGetSymbolAddress((void**)&sp, g_s);

    const int M = BATCH * SEQ;                       // 8192
    const long long sQK = (long long)SEQ * DIM;
    const long long sVT = (long long)DIM * SEQ;
    const long long sSS = (long long)SEQ * SEQ;

    // 1) QKV projections: [8192,1024] @ [1024,1024]^T + bias
    {
        dim3 grid(DIM / BN, M / BM, 1);
        tc_gemm<<<grid, THREADS>>>(X, Wq, bq, qp,  DIM, DIM, DIM, DIM, 1.0f, 0, 0, 0, 0);
        tc_gemm<<<grid, THREADS>>>(X, Wk, bk, kp,  DIM, DIM, DIM, DIM, 1.0f, 0, 0, 0, 0);
        tc_gemm<<<grid, THREADS>>>(X, Wv, bv, vtp, DIM, DIM, DIM, DIM, 1.0f,
                                   F_TRANS_STORE, 0, 0, 0);
    }

    // 2) scores = (Q @ K^T) / 32, causal tiles only
    {
        dim3 grid(SEQ / BN, SEQ / BM, BATCH);
        tc_gemm<<<grid, THREADS>>>(qp, kp, nullptr, sp, DIM, DIM, DIM, SEQ,
                                   0.03125f, F_CAUSAL_SKIP, sQK, sQK, sSS);
    }

    // 3) causal softmax
    {
        dim3 grid(SEQ, BATCH);
        causal_softmax<<<grid, 256>>>(sp, SEQ);
    }

    // 4) out = P @ Vt^T  (NT form; K limited to causal boundary)
    {
        dim3 grid(DIM / BN, SEQ / BM, BATCH);
        tc_gemm<<<grid, THREADS>>>(sp, vtp, nullptr, out, SEQ, SEQ, SEQ, DIM,
                                   1.0f, F_CAUSAL_KLIM, sSS, sVT, sQK);
    }
}

// round 6
// speedup vs baseline: 2.4949x; 1.0214x over previous
#include <cuda_runtime.h>
#include <cuda_fp16.h>
#include <cstdint>
#include <math.h>

// Problem constants
#define BATCH 4
#define SEQ   2048
#define DIM   1024

#define BM 128
#define BN 128
#define KC 32            // K elements (halfs) per stage
#define THREADS 256

// flags
#define F_CAUSAL_SKIP  1
#define F_CAUSAL_KLIM  2
#define F_TRANS_STORE  4
#define F_OUT_HALF     8

#define NX (BATCH * SEQ * DIM)   // 8M
#define NW (DIM * DIM)           // 1M
#define NS (BATCH * SEQ * SEQ)   // 16M

// smem: 4 tiles (Ah,Al,Bh,Bl) x 8KB = 32KB per stage, 2 stages
#define TILE_B  (BM * KC * 2)    // 8192
#define STAGE_B (4 * TILE_B)     // 32768
#define SMEM_TOTAL (2 * STAGE_B) // 65536

// Scratch (allocation-free)
__device__ __half g_xh[NX],  g_xl[NX];
__device__ __half g_wqh[NW], g_wql[NW];
__device__ __half g_wkh[NW], g_wkl[NW];
__device__ __half g_wvh[NW], g_wvl[NW];
__device__ __half g_qh[NX],  g_ql[NX];
__device__ __half g_kh[NX],  g_kl[NX];
__device__ __half g_vth[NX], g_vtl[NX];   // V transposed [b][d][s]
__device__ float  g_s[NS];
__device__ __half g_ph[NS],  g_pl[NS];

__device__ __forceinline__ uint32_t smem_u32(const void* p) {
    uint32_t a;
    asm("{ .reg .u64 t; cvta.to.shared.u64 t, %1; cvt.u32.u64 %0, t; }" : "=r"(a) : "l"(p));
    return a;
}

#define LDMATRIX_X4(r0, r1, r2, r3, addr)                                      \
    asm volatile("ldmatrix.sync.aligned.m8n8.x4.shared.b16 {%0,%1,%2,%3}, [%4];" \
        : "=r"(r0), "=r"(r1), "=r"(r2), "=r"(r3) : "r"(addr))

#define MMA16816(d0, d1, d2, d3, a0, a1, a2, a3, b0, b1)                       \
    asm volatile("mma.sync.aligned.m16n8k16.row.col.f32.f16.f16.f32 "          \
        "{%0,%1,%2,%3},{%4,%5,%6,%7},{%8,%9},{%0,%1,%2,%3};"                   \
        : "+f"(d0), "+f"(d1), "+f"(d2), "+f"(d3)                               \
        : "r"(a0), "r"(a1), "r"(a2), "r"(a3), "r"(b0), "r"(b1))

#define CP16(dst, src) \
    asm volatile("cp.async.cg.shared.global [%0], [%1], 16;" :: "r"(dst), "l"(src))
#define CP_COMMIT()  asm volatile("cp.async.commit_group;" ::: "memory")
#define CP_WAIT1()   asm volatile("cp.async.wait_group 1;" ::: "memory")
#define CP_WAIT0()   asm volatile("cp.async.wait_group 0;" ::: "memory")

// SW64 swizzle for 64-byte rows (KC=32 halfs)
__device__ __forceinline__ uint32_t sw64(uint32_t off) {
    return off ^ ((off >> 3) & 0x30);
}

// split fp32 -> fp16 hi + fp16 residual
__device__ __forceinline__ void split1(float x, __half& h, __half& l) {
    h = __float2half_rn(x);
    l = __float2half_rn(x - __half2float(h));
}

// ---------------------------------------------------------------------------
// NT GEMM, fp16 hi/lo pre-split inputs: C = scale * (A @ B^T) + bias
// A{h,l} [M,K], B{h,l} [N,K] halfs, K-major. cp.async double-buffered.
// ---------------------------------------------------------------------------
__global__ void __launch_bounds__(THREADS, 2)
tc_gemm(const __half* __restrict__ Ah, const __half* __restrict__ Al,
        const __half* __restrict__ Bh, const __half* __restrict__ Bl,
        const float* __restrict__ bias,
        float* __restrict__ C, __half* __restrict__ Ch, __half* __restrict__ Cl,
        int K, int ldA, int ldB, int ldC, float scale, int flags,
        long long sA, long long sB, long long sC)
{
    const int bx = blockIdx.x, by = blockIdx.y, bz = blockIdx.z;
    if ((flags & F_CAUSAL_SKIP) && bx > by) return;

    extern __shared__ __align__(1024) char smem[];
    const uint32_t sbase = smem_u32(smem);

    const int tid  = threadIdx.x;
    const int lane = tid & 31;
    const int wid  = tid >> 5;
    const int wm   = wid & 1;          // 2 m-groups of 64 rows
    const int wn   = wid >> 1;         // 4 n-groups of 32 cols

    int kend = K;
    if (flags & F_CAUSAL_KLIM) kend = min(K, (by + 1) * BM);
    const int nkb = kend / KC;

    const size_t aoff = (size_t)bz * sA + (size_t)by * BM * ldA;
    const size_t boff = (size_t)bz * sB + (size_t)bx * BN * ldB;
    const __half* pAh = Ah + aoff;
    const __half* pAl = Al + aoff;
    const __half* pBh = Bh + boff;
    const __half* pBl = Bl + boff;

    // loader coords: each thread owns 2 consecutive 16B chunks of one row
    const int lrow = tid >> 1;                // 0..127
    const int lc   = (tid & 1) * 2;           // 16B chunk base (0 or 2)
    const uint32_t so0 = sw64(lrow * 64 + lc * 16);
    const uint32_t so1 = sw64(lrow * 64 + lc * 16 + 16);
    const size_t gA = (size_t)lrow * ldA + lc * 8;
    const size_t gB = (size_t)lrow * ldB + lc * 8;

#define LOAD_STAGE(buf, kb) do {                                               \
        const int _k0 = (kb) * KC;                                             \
        const uint32_t _sb = sbase + (buf) * STAGE_B;                          \
        CP16(_sb + so0,              pAh + gA + _k0);                          \
        CP16(_sb + so1,              pAh + gA + _k0 + 8);                      \
        CP16(_sb + TILE_B + so0,     pAl + gA + _k0);                          \
        CP16(_sb + TILE_B + so1,     pAl + gA + _k0 + 8);                      \
        CP16(_sb + 2*TILE_B + so0,   pBh + gB + _k0);                          \
        CP16(_sb + 2*TILE_B + so1,   pBh + gB + _k0 + 8);                      \
        CP16(_sb + 3*TILE_B + so0,   pBl + gB + _k0);                          \
        CP16(_sb + 3*TILE_B + so1,   pBl + gB + _k0 + 8);                      \
        CP_COMMIT();                                                           \
    } while (0)

    float acc[4][4][4];
#pragma unroll
    for (int i = 0; i < 4; i++)
#pragma unroll
        for (int j = 0; j < 4; j++)
#pragma unroll
            for (int c = 0; c < 4; c++) acc[i][j][c] = 0.0f;

    // ldmatrix lane-address components
    const int lr  = lane & 7;
    const int grp = lane >> 3;
    const int lm_row_off = lr + ((grp & 1) << 3);
    const int lm_col_off = (grp >> 1) << 4;

    LOAD_STAGE(0, 0);

    for (int kb = 0; kb < nkb; kb++) {
        const int buf = kb & 1;
        if (kb + 1 < nkb) {
            LOAD_STAGE(buf ^ 1, kb + 1);
            CP_WAIT1();
        } else {
            CP_WAIT0();
        }
        __syncthreads();

        const uint32_t uAh = sbase + buf * STAGE_B;
        const uint32_t uAl = uAh + TILE_B;
        const uint32_t uBh = uAh + 2 * TILE_B;
        const uint32_t uBl = uAh + 3 * TILE_B;

#pragma unroll
        for (int ks = 0; ks < 2; ks++) {
            const uint32_t kbyte = ks * 32 + lm_col_off;

            uint32_t bh[2][4], bl[2][4];
#pragma unroll
            for (int ng = 0; ng < 2; ng++) {
                int nrow = wn * 32 + ng * 16 + lm_row_off;
                uint32_t off = sw64(nrow * 64 + kbyte);
                LDMATRIX_X4(bh[ng][0], bh[ng][1], bh[ng][2], bh[ng][3], uBh + off);
                LDMATRIX_X4(bl[ng][0], bl[ng][1], bl[ng][2], bl[ng][3], uBl + off);
            }

#pragma unroll
            for (int mt = 0; mt < 4; mt++) {
                int mrow = wm * 64 + mt * 16 + lm_row_off;
                uint32_t off = sw64(mrow * 64 + kbyte);
                uint32_t ah[4], al[4];
                LDMATRIX_X4(ah[0], ah[1], ah[2], ah[3], uAh + off);
                LDMATRIX_X4(al[0], al[1], al[2], al[3], uAl + off);

#pragma unroll
                for (int nt = 0; nt < 4; nt++) {
                    const int ng = nt >> 1, s = nt & 1;
                    float* d = acc[mt][nt];
                    // hi*hi + hi*lo + lo*hi  (lo*lo dropped, ~2^-22)
                    MMA16816(d[0], d[1], d[2], d[3],
                             ah[0], ah[1], ah[2], ah[3], bh[ng][s], bh[ng][s + 2]);
                    MMA16816(d[0], d[1], d[2], d[3],
                             ah[0], ah[1], ah[2], ah[3], bl[ng][s], bl[ng][s + 2]);
                    MMA16816(d[0], d[1], d[2], d[3],
                             al[0], al[1], al[2], al[3], bh[ng][s], bh[ng][s + 2]);
                }
            }
        }
        __syncthreads();
    }

    // ---- epilogue ----
    const int r0 = by * BM + wm * 64 + (lane >> 2);
    const int c0 = bx * BN + wn * 32 + ((lane & 3) << 1);

    if (!(flags & F_OUT_HALF)) {
        // fp32 output (scores / final out)
#pragma unroll
        for (int mt = 0; mt < 4; mt++) {
#pragma unroll
            for (int nt = 0; nt < 4; nt++) {
                int row = r0 + mt * 16;
                int col = c0 + nt * 8;
                float b0 = bias ? bias[col] : 0.0f;
                float b1 = bias ? bias[col + 1] : 0.0f;
                float* dst = C + (size_t)bz * sC + (size_t)row * ldC + col;
                *(float2*)dst = make_float2(acc[mt][nt][0] * scale + b0,
                                            acc[mt][nt][1] * scale + b1);
                *(float2*)(dst + 8ull * ldC) = make_float2(acc[mt][nt][2] * scale + b0,
                                                           acc[mt][nt][3] * scale + b1);
            }
        }
    } else if (!(flags & F_TRANS_STORE)) {
        // hi/lo half output, row-major (Q / K projections)
#pragma unroll
        for (int mt = 0; mt < 4; mt++) {
#pragma unroll
            for (int nt = 0; nt < 4; nt++) {
                int row = r0 + mt * 16;
                int col = c0 + nt * 8;
                float b0 = bias[col], b1 = bias[col + 1];
                float v0 = acc[mt][nt][0] * scale + b0;
                float v1 = acc[mt][nt][1] * scale + b1;
                float v2 = acc[mt][nt][2] * scale + b0;
                float v3 = acc[mt][nt][3] * scale + b1;
                __half h0, h1, h2, h3, l0, l1, l2, l3;
                split1(v0, h0, l0); split1(v1, h1, l1);
                split1(v2, h2, l2); split1(v3, h3, l3);
                size_t o0 = (size_t)bz * sC + (size_t)row * ldC + col;
                size_t o1 = o0 + 8ull * ldC;
                *(__half2*)(Ch + o0) = __halves2half2(h0, h1);
                *(__half2*)(Cl + o0) = __halves2half2(l0, l1);
                *(__half2*)(Ch + o1) = __halves2half2(h2, h3);
                *(__half2*)(Cl + o1) = __halves2half2(l2, l3);
            }
        }
    } else {
        // hi/lo half output, transposed (V projection -> [b][d][s])
#pragma unroll
        for (int mt = 0; mt < 4; mt++) {
            int row = r0 + mt * 16;
            int b = row >> 11;
            int s = row & (SEQ - 1);
            __half* dh = g_vth + (size_t)b * DIM * SEQ + s;
            __half* dl = g_vtl + (size_t)b * DIM * SEQ + s;
#pragma unroll
            for (int nt = 0; nt < 4; nt++) {
                int col = c0 + nt * 8;
                float b0 = bias[col], b1 = bias[col + 1];
                __half h, l;
                split1(acc[mt][nt][0] * scale + b0, h, l);
                dh[(size_t)col * SEQ] = h;       dl[(size_t)col * SEQ] = l;
                split1(acc[mt][nt][1] * scale + b1, h, l);
                dh[(size_t)(col + 1) * SEQ] = h; dl[(size_t)(col + 1) * SEQ] = l;
                split1(acc[mt][nt][2] * scale + b0, h, l);
                dh[(size_t)col * SEQ + 8] = h;   dl[(size_t)col * SEQ + 8] = l;
                split1(acc[mt][nt][3] * scale + b1, h, l);
                dh[(size_t)(col + 1) * SEQ + 8] = h; dl[(size_t)(col + 1) * SEQ + 8] = l;
            }
        }
    }
#undef LOAD_STAGE
}

// ---------------------------------------------------------------------------
// elementwise fp32 -> (hi, lo) fp16 split, float4-vectorized
// ---------------------------------------------------------------------------
__global__ void __launch_bounds__(256)
split_f32(const float* __restrict__ x, __half* __restrict__ h,
          __half* __restrict__ l, int n4)
{
    int i = blockIdx.x * blockDim.x + threadIdx.x;
    if (i >= n4) return;
    float4 v = ((const float4*)x)[i];
    __half hx = __float2half_rn(v.x), hy = __float2half_rn(v.y);
    __half hz = __float2half_rn(v.z), hw = __float2half_rn(v.w);
    __half2 H0 = __halves2half2(hx, hy), H1 = __halves2half2(hz, hw);
    __half2 L0 = __floats2half2_rn(v.x - __half2float(hx), v.y - __half2float(hy));
    __half2 L1 = __floats2half2_rn(v.z - __half2float(hz), v.w - __half2float(hw));
    ((__half2*)h)[i * 2]     = H0;
    ((__half2*)h)[i * 2 + 1] = H1;
    ((__half2*)l)[i * 2]     = L0;
    ((__half2*)l)[i * 2 + 1] = L1;
}

// ---------------------------------------------------------------------------
// Causal row softmax: fp32 scores -> hi/lo fp16 probabilities (zero tails)
// ---------------------------------------------------------------------------
__global__ void __launch_bounds__(256)
causal_softmax(const float* __restrict__ S, __half* __restrict__ Ph,
               __half* __restrict__ Pl, int seq)
{
    int r = blockIdx.x;
    int b = blockIdx.y;
    size_t base = ((size_t)b * seq + (size_t)r) * seq;
    const float* row = S + base;
    int n = r + 1;
    int tid = threadIdx.x;

    __shared__ float red[256];

    float m = -1e30f;
    for (int j = tid; j < n; j += 256) m = fmaxf(m, row[j]);
    red[tid] = m; __syncthreads();
    for (int s = 128; s > 0; s >>= 1) {
        if (tid < s) red[tid] = fmaxf(red[tid], red[tid + s]);
        __syncthreads();
    }
    m = red[0]; __syncthreads();

    float ev[8];
    int cnt = 0;
    float sum = 0.0f;
    for (int j = tid; j < n; j += 256) {
        float e = __expf(row[j] - m);
        ev[cnt++] = e;
        sum += e;
    }
    red[tid] = sum; __syncthreads();
    for (int s = 128; s > 0; s >>= 1) {
        if (tid < s) red[tid] += red[tid + s];
        __syncthreads();
    }
    float inv = 1.0f / red[0];

    cnt = 0;
    for (int j = tid; j < n; j += 256) {
        float p = ev[cnt++] * inv;
        __half h = __float2half_rn(p);
        Ph[base + j] = h;
        Pl[base + j] = __float2half_rn(p - __half2float(h));
    }
    __half z = __float2half_rn(0.0f);
    for (int j = n + tid; j < seq; j += 256) {
        Ph[base + j] = z;
        Pl[base + j] = z;
    }
}

// ---------------------------------------------------------------------------
extern "C" void kernel_launch(void* const* d_in, const int* in_sizes, int n_in,
                              void* d_out, int out_size)
{
    const float* X  = (const float*)d_in[0];
    const float* Wq = (const float*)d_in[1];
    const float* bq = (const float*)d_in[2];
    const float* Wk = (const float*)d_in[3];
    const float* bk = (const float*)d_in[4];
    const float* Wv = (const float*)d_in[5];
    const float* bv = (const float*)d_in[6];
    float* out = (float*)d_out;

    __half *xh, *xl, *wqh, *wql, *wkh, *wkl, *wvh, *wvl;
    __half *qh, *ql, *kh, *kl, *vth, *vtl, *ph, *pl;
    float* sp;
    cudaGetSymbolAddress((void**)&xh,  g_xh);  cudaGetSymbolAddress((void**)&xl,  g_xl);
    cudaGetSymbolAddress((void**)&wqh, g_wqh); cudaGetSymbolAddress((void**)&wql, g_wql);
    cudaGetSymbolAddress((void**)&wkh, g_wkh); cudaGetSymbolAddress((void**)&wkl, g_wkl);
    cudaGetSymbolAddress((void**)&wvh, g_wvh); cudaGetSymbolAddress((void**)&wvl, g_wvl);
    cudaGetSymbolAddress((void**)&qh,  g_qh);  cudaGetSymbolAddress((void**)&ql,  g_ql);
    cudaGetSymbolAddress((void**)&kh,  g_kh);  cudaGetSymbolAddress((void**)&kl,  g_kl);
    cudaGetSymbolAddress((void**)&vth, g_vth); cudaGetSymbolAddress((void**)&vtl, g_vtl);
    cudaGetSymbolAddress((void**)&ph,  g_ph);  cudaGetSymbolAddress((void**)&pl,  g_pl);
    cudaGetSymbolAddress((void**)&sp,  g_s);

    static int smem_set = 0;
    if (!smem_set) {
        cudaFuncSetAttribute(tc_gemm, cudaFuncAttributeMaxDynamicSharedMemorySize, SMEM_TOTAL);
        smem_set = 1;
    }

    const int M = BATCH * SEQ;                       // 8192
    const long long sQK = (long long)SEQ * DIM;
    const long long sVT = (long long)DIM * SEQ;
    const long long sSS = (long long)SEQ * SEQ;

    // 0) pre-split inputs into hi/lo fp16
    split_f32<<<(NX / 4 + 255) / 256, 256>>>(X,  xh,  xl,  NX / 4);
    split_f32<<<(NW / 4 + 255) / 256, 256>>>(Wq, wqh, wql, NW / 4);
    split_f32<<<(NW / 4 + 255) / 256, 256>>>(Wk, wkh, wkl, NW / 4);
    split_f32<<<(NW / 4 + 255) / 256, 256>>>(Wv, wvh, wvl, NW / 4);

    // 1) QKV projections (output hi/lo fp16; V transposed)
    {
        dim3 grid(DIM / BN, M / BM, 1);
        tc_gemm<<<grid, THREADS, SMEM_TOTAL>>>(xh, xl, wqh, wql, bq, nullptr, qh, ql,
                                               DIM, DIM, DIM, DIM, 1.0f, F_OUT_HALF, 0, 0, 0);
        tc_gemm<<<grid, THREADS, SMEM_TOTAL>>>(xh, xl, wkh, wkl, bk, nullptr, kh, kl,
                                               DIM, DIM, DIM, DIM, 1.0f, F_OUT_HALF, 0, 0, 0);
        tc_gemm<<<grid, THREADS, SMEM_TOTAL>>>(xh, xl, wvh, wvl, bv, nullptr, vth, vtl,
                                               DIM, DIM, DIM, DIM, 1.0f,
                                               F_OUT_HALF | F_TRANS_STORE, 0, 0, 0);
    }

    // 2) scores = (Q @ K^T) / 32, fp32, causal tiles only
    {
        dim3 grid(SEQ / BN, SEQ / BM, BATCH);
        tc_gemm<<<grid, THREADS, SMEM_TOTAL>>>(qh, ql, kh, kl, nullptr, sp, nullptr, nullptr,
                                               DIM, DIM, DIM, SEQ, 0.03125f,
                                               F_CAUSAL_SKIP, sQK, sQK, sSS);
    }

    // 3) causal softmax -> hi/lo fp16 P
    {
        dim3 grid(SEQ, BATCH);
        causal_softmax<<<grid, 256>>>(sp, ph, pl, SEQ);
    }

    // 4) out = P @ Vt^T  (fp32 out; K limited to causal boundary)
    {
        dim3 grid(DIM / BN, SEQ / BM, BATCH);
        tc_gemm<<<grid, THREADS, SMEM_TOTAL>>>(ph, pl, vth, vtl, nullptr, out, nullptr, nullptr,
                                               SEQ, SEQ, SEQ, DIM, 1.0f,
                                               F_CAUSAL_KLIM, sSS, sVT, sQK);
    }
}